// round 1
// baseline (speedup 1.0000x reference)
#include <cuda_runtime.h>
#include <cstdint>

typedef unsigned long long ull;

// ---------------------------------------------------------------------------
// Problem geometry (d = 32 is structural; B and NC derived from in_sizes)
// ---------------------------------------------------------------------------
#define DZ 32

// Scratch (static device globals: no allocation allowed)
__device__ float g_mu_dup[4096 * 2 * DZ];  // duplicated, kappa*log2e-scaled unit mu rows
__device__ float g_partials[1024];         // per-block sums of ln(s_j)

// ---------------------------------------------------------------------------
// f32x2 packed helpers (FFMA2 path — ptxas never auto-fuses; see SASS_QUICKREF)
// ---------------------------------------------------------------------------
static __device__ __forceinline__ ull pack2f(float lo, float hi) {
    ull r; asm("mov.b64 %0, {%1, %2};" : "=l"(r) : "f"(lo), "f"(hi)); return r;
}
static __device__ __forceinline__ void unpack2f(ull v, float& lo, float& hi) {
    asm("mov.b64 {%0, %1}, %2;" : "=f"(lo), "=f"(hi) : "l"(v));
}
static __device__ __forceinline__ void unpack2i(ull v, int& lo, int& hi) {
    asm("mov.b64 {%0, %1}, %2;" : "=r"(lo), "=r"(hi) : "l"(v));
}
#define FFMA2(d, a, b, c) asm("fma.rn.f32x2 %0, %1, %2, %3;" : "=l"(d) : "l"(a), "l"(b), "l"(c))
#define FADD2(d, a, b)    asm("add.rn.f32x2 %0, %1, %2;"     : "=l"(d) : "l"(a), "l"(b))

// ---------------------------------------------------------------------------
// Kernel 1: normalize mu rows, scale by kappa*log2(e), store duplicated pairs
// One warp per row. Also leaves g_partials to be fully overwritten by main.
// ---------------------------------------------------------------------------
__global__ void vmf_prep(const float* __restrict__ mu,
                         const float* __restrict__ kap_p, int B)
{
    const int warp = (blockIdx.x * blockDim.x + threadIdx.x) >> 5;
    const int lane = threadIdx.x & 31;
    if (warp >= B) return;

    float v = __ldg(mu + (size_t)warp * DZ + lane);
    float ss = v * v;
    #pragma unroll
    for (int o = 16; o > 0; o >>= 1)
        ss += __shfl_xor_sync(0xFFFFFFFFu, ss, o);

    float r = rsqrtf(ss);
    r = r * fmaf(-0.5f * ss * r, r, 1.5f);     // one Newton step -> ~1e-7 rel
    const float L2E = 1.4426950408889634f;
    float w = v * r * (__ldg(kap_p) * L2E);

    ((float2*)g_mu_dup)[(size_t)warp * DZ + lane] = make_float2(w, w);
}

// ---------------------------------------------------------------------------
// Kernel 2: fused GEMM + exp2-sum.
// Each thread owns 2 columns (one f32x2 lane pair), loops all B mu rows,
// accumulating s_j = sum_i 2^(kappa*l2e*(dot-1)).  exp2 via FMA-pipe poly.
// ---------------------------------------------------------------------------
__global__ void __launch_bounds__(256) vmf_main(
    const float* __restrict__ z, const float* __restrict__ kap_p,
    int B, int NC)
{
    __shared__ __align__(16) float smu[128 * 2 * DZ];   // 32KB tile, duplicated rows
    __shared__ float red[8];

    const int tid = threadIdx.x;
    const int j0  = blockIdx.x * 512 + tid * 2;
    const int jj0 = min(j0,     NC - 1);
    const int jj1 = min(j0 + 1, NC - 1);

    const float L2E = 1.4426950408889634f;
    const float kappa = __ldg(kap_p);
    const float bias  = -kappa * L2E;            // fixed bias = -kappa in log2 units

    // packed constants
    const ull bias2  = pack2f(bias, bias);
    const ull MAGIC2 = 0x4B4000004B400000ULL;    // 2^23 * 1.5 (x2)
    const ull NMAGIC2= 0xCB400000CB400000ULL;    // -2^23 * 1.5
    const ull NEG1_2 = 0xBF800000BF800000ULL;    // -1.0f (x2)
    const ull C5 = pack2f(1.3333558e-3f, 1.3333558e-3f);
    const ull C4 = pack2f(9.6181291e-3f, 9.6181291e-3f);
    const ull C3 = pack2f(5.5504109e-2f, 5.5504109e-2f);
    const ull C2 = pack2f(2.4022651e-1f, 2.4022651e-1f);
    const ull C1 = pack2f(6.9314718e-1f, 6.9314718e-1f);
    const ull C0 = pack2f(1.0f, 1.0f);
    const int IBLO = 0x4B400000 - 126;           // clamp: n >= -126
    const int KADD = 127 - 0x4B400000;

    // Load this thread's two z vectors, interleaved as f32x2 pairs
    ull zp[DZ];
    {
        const float4* p0 = (const float4*)(z + (size_t)jj0 * DZ);
        const float4* p1 = (const float4*)(z + (size_t)jj1 * DZ);
        #pragma unroll
        for (int q = 0; q < 8; q++) {
            float4 a = __ldg(p0 + q);
            float4 b = __ldg(p1 + q);
            zp[q*4+0] = pack2f(a.x, b.x);
            zp[q*4+1] = pack2f(a.y, b.y);
            zp[q*4+2] = pack2f(a.z, b.z);
            zp[q*4+3] = pack2f(a.w, b.w);
        }
    }

    float s0 = 0.f, s1 = 0.f;

#define EXPADD(Y) do {                                                         \
        ull t_, u_, f_, p_;                                                    \
        FADD2(t_, (Y), MAGIC2);            /* t = rint(y) + magic      */      \
        FADD2(u_, t_, NMAGIC2);            /* u = n (as float pair)    */      \
        FFMA2(f_, u_, NEG1_2, (Y));        /* f = y - n, |f| <= 0.5    */      \
        p_ = C5;                                                               \
        FFMA2(p_, p_, f_, C4); FFMA2(p_, p_, f_, C3);                          \
        FFMA2(p_, p_, f_, C2); FFMA2(p_, p_, f_, C1);                          \
        FFMA2(p_, p_, f_, C0);                                                 \
        int i0_, i1_; unpack2i(t_, i0_, i1_);                                  \
        i0_ = max(i0_, IBLO); i1_ = max(i1_, IBLO);                            \
        float sc0_ = __int_as_float((i0_ + KADD) << 23);                       \
        float sc1_ = __int_as_float((i1_ + KADD) << 23);                       \
        float p0_, p1_; unpack2f(p_, p0_, p1_);                                \
        s0 = fmaf(sc0_, p0_, s0);                                              \
        s1 = fmaf(sc1_, p1_, s1);                                              \
    } while (0)

    for (int t = 0; t < B; t += 128) {
        const int nr = min(128, B - t);
        // cooperative tile copy (rows pre-duplicated -> straight float4 copy)
        {
            const float4* src = ((const float4*)g_mu_dup) + (size_t)t * 16;
            float4* dst = (float4*)smu;
            for (int i = tid; i < nr * 16; i += 256) dst[i] = src[i];
        }
        __syncthreads();

        for (int r = 0; r < nr; r += 2) {
            const ulonglong2* m0 = (const ulonglong2*)(smu + (size_t)r * 64);
            const ulonglong2* m1 = (const ulonglong2*)(smu + (size_t)(r + 1) * 64);
            ull a0 = bias2, a1 = bias2;
            #pragma unroll
            for (int k = 0; k < 16; k++) {
                ulonglong2 u = m0[k];
                ulonglong2 v = m1[k];
                FFMA2(a0, u.x, zp[2*k],     a0);
                FFMA2(a1, v.x, zp[2*k],     a1);
                FFMA2(a0, u.y, zp[2*k + 1], a0);
                FFMA2(a1, v.y, zp[2*k + 1], a1);
            }
            EXPADD(a0);
            EXPADD(a1);
        }
        __syncthreads();
    }
#undef EXPADD

    // per-thread contribution: ln(s) for valid columns
    float contrib = 0.f;
    if (j0     < NC) contrib += logf(fmaxf(s0, 1e-37f));
    if (j0 + 1 < NC) contrib += logf(fmaxf(s1, 1e-37f));

    #pragma unroll
    for (int o = 16; o > 0; o >>= 1)
        contrib += __shfl_xor_sync(0xFFFFFFFFu, contrib, o);
    if ((tid & 31) == 0) red[tid >> 5] = contrib;
    __syncthreads();
    if (tid == 0) {
        float tot = 0.f;
        #pragma unroll
        for (int w = 0; w < 8; w++) tot += red[w];
        g_partials[blockIdx.x] = tot;     // deterministic (no atomics)
    }
}

// ---------------------------------------------------------------------------
// Kernel 3: combine partials, add constants, write scalar output
// okl = logC_kappa + kappa - ln(B) - logC_zero + mean_j ln(s_j)
// ---------------------------------------------------------------------------
__global__ void vmf_final(const float* __restrict__ kap_p,
                          const float* __restrict__ lck_p,
                          const float* __restrict__ lcz_p,
                          float* __restrict__ out,
                          int nblocks, int B, int NC)
{
    __shared__ float red[4];
    const int tid = threadIdx.x;
    float v = 0.f;
    for (int i = tid; i < nblocks; i += blockDim.x) v += g_partials[i];
    #pragma unroll
    for (int o = 16; o > 0; o >>= 1)
        v += __shfl_xor_sync(0xFFFFFFFFu, v, o);
    if ((tid & 31) == 0) red[tid >> 5] = v;
    __syncthreads();
    if (tid == 0) {
        float tot = red[0] + red[1] + red[2] + red[3];
        float okl = __ldg(lck_p) + __ldg(kap_p)
                  - logf((float)B) - __ldg(lcz_p)
                  + tot / (float)NC;
        out[0] = okl;
    }
}

// ---------------------------------------------------------------------------
// Launch: prep -> main -> final (all default stream, graph-capturable,
// allocation-free, deterministic)
// ---------------------------------------------------------------------------
extern "C" void kernel_launch(void* const* d_in, const int* in_sizes, int n_in,
                              void* d_out, int out_size)
{
    const float* mu  = (const float*)d_in[0];
    const float* z   = (const float*)d_in[1];
    const float* kap = (const float*)d_in[2];
    const float* lck = (const float*)d_in[3];
    const float* lcz = (const float*)d_in[4];

    const int B  = in_sizes[0] / DZ;   // 2048
    const int NC = in_sizes[1] / DZ;   // 65536 sample columns

    const int prepBlocks = (B + 7) / 8;            // 8 warps/block, 1 warp/row
    vmf_prep<<<prepBlocks, 256>>>(mu, kap, B);

    const int mainBlocks = (NC + 511) / 512;       // 512 cols/block
    vmf_main<<<mainBlocks, 256>>>(z, kap, B, NC);

    vmf_final<<<1, 128>>>(kap, lck, lcz, (float*)d_out, mainBlocks, B, NC);
}

// round 4
// speedup vs baseline: 1.8428x; 1.8428x over previous
#include <cuda_runtime.h>
#include <cstdint>

#define DZ 32
#define L2E 1.4426950408889634f

// ---------------------------------------------------------------------------
// Static device scratch (no runtime allocation allowed)
// ---------------------------------------------------------------------------
__device__ float g_mu_hi[4096 * DZ];   // normalized*kappa*log2e, tf32-hi part
__device__ float g_mu_lo[4096 * DZ];   // residual (lo) part
__device__ float g_partials[1024];

// ---------------------------------------------------------------------------
// Helpers
// ---------------------------------------------------------------------------
static __device__ __forceinline__ uint32_t s2u(const void* p) {
    uint32_t a;
    asm("{ .reg .u64 t; cvta.to.shared.u64 t, %1; cvt.u32.u64 %0, t; }" : "=r"(a) : "l"(p));
    return a;
}
static __device__ __forceinline__ void cp16(uint32_t saddr, const void* gaddr) {
    asm volatile("cp.async.cg.shared.global [%0], [%1], 16;"
                 :: "r"(saddr), "l"(__cvta_generic_to_global(gaddr)) : "memory");
}
static __device__ __forceinline__ float ex2f(float x) {
    float r; asm("ex2.approx.f32 %0, %1;" : "=f"(r) : "f"(x)); return r;
}
// m16n8k8 tf32 MMA: D(f32) += A(tf32) * B(tf32)
static __device__ __forceinline__ void mma8(float* d, const uint32_t* a, const uint32_t* b) {
    asm volatile(
        "mma.sync.aligned.m16n8k8.row.col.f32.tf32.tf32.f32 "
        "{%0,%1,%2,%3},{%4,%5,%6,%7},{%8,%9},{%0,%1,%2,%3};"
        : "+f"(d[0]), "+f"(d[1]), "+f"(d[2]), "+f"(d[3])
        : "r"(a[0]), "r"(a[1]), "r"(a[2]), "r"(a[3]), "r"(b[0]), "r"(b[1]));
}

// ---------------------------------------------------------------------------
// Prep: normalize mu rows, scale by kappa*log2e, split into tf32 hi + residual
// One warp per row.
// ---------------------------------------------------------------------------
__global__ void vmf_prep_mu(const float* __restrict__ mu,
                            const float* __restrict__ kap_p, int B)
{
    const int n = (blockIdx.x * blockDim.x + threadIdx.x) >> 5;
    const int k = threadIdx.x & 31;
    if (n >= B) return;

    float v = __ldg(mu + (size_t)n * DZ + k);
    float ss = v * v;
    #pragma unroll
    for (int o = 16; o > 0; o >>= 1) ss += __shfl_xor_sync(0xFFFFFFFFu, ss, o);
    float r = rsqrtf(ss);
    r = r * fmaf(-0.5f * ss * r, r, 1.5f);          // Newton -> ~1e-7 rel
    float w = v * r * (__ldg(kap_p) * L2E);

    float hi = __uint_as_float(__float_as_uint(w) & 0xFFFFE000u);
    g_mu_hi[n * DZ + k] = hi;
    g_mu_lo[n * DZ + k] = w - hi;
}

// ---------------------------------------------------------------------------
// Main: 256 z rows per CTA (8 warps x 32 rows held in A fragments).
// mu streamed in 64-row chunks through double-buffered smem (cp.async).
// tf32 hi/lo split GEMM on tensor pipe; exp2-sum epilogue on C fragments
// with whole-block underflow skip (most mu chunks contribute ~0).
// ---------------------------------------------------------------------------
__global__ void __launch_bounds__(256, 2) vmf_main(
    const float* __restrict__ z, const float* __restrict__ kap_p,
    int B, int NC)
{
    __shared__ __align__(16) float smh[2][64 * DZ];   // mu hi tiles (8KB each)
    __shared__ __align__(16) float sml[2][64 * DZ];   // mu lo tiles
    __shared__ float s_red[8];

    const int tid  = threadIdx.x;
    const int wid  = tid >> 5;
    const int lane = tid & 31;
    const int g    = lane >> 2;        // group row 0..7
    const int l4   = lane & 3;
    const int g4   = g << 2;           // swizzle key

    const float bias = -__ldg(kap_p) * L2E;
    const float thr  = -126.0f - bias;   // raw-logit threshold for skip

    // ---- Load this warp's 32 z rows into tf32-split A fragments (held) ----
    const int zr = blockIdx.x * 256 + wid * 32;
    uint32_t ahi[2][4][4], alo[2][4][4];
    #pragma unroll
    for (int m = 0; m < 2; m++) {
        const int r0 = zr + m * 16 + g;
        const int r1 = r0 + 8;
        #pragma unroll
        for (int j = 0; j < 4; j++) {
            const int c0 = j * 8 + l4;
            float f0 = __ldg(z + (size_t)r0 * DZ + c0);
            float f1 = __ldg(z + (size_t)r1 * DZ + c0);
            float f2 = __ldg(z + (size_t)r0 * DZ + c0 + 4);
            float f3 = __ldg(z + (size_t)r1 * DZ + c0 + 4);
            float v[4] = {f0, f1, f2, f3};
            #pragma unroll
            for (int q = 0; q < 4; q++) {
                uint32_t uh = __float_as_uint(v[q]) & 0xFFFFE000u;
                ahi[m][j][q] = uh;
                alo[m][j][q] = __float_as_uint(v[q] - __uint_as_float(uh));
            }
        }
    }

    const uint32_t sh_base[2] = { s2u(&smh[0][0]), s2u(&smh[1][0]) };
    const uint32_t sl_base[2] = { s2u(&sml[0][0]), s2u(&sml[1][0]) };

    const int T = B >> 6;              // 64-mu chunks (32)

    // chunk copy: 64 rows x 32 floats = 512 float4 per kind -> 2 per thread
    auto copy_chunk = [&](int t, int buf) {
        const float4* srch = (const float4*)(g_mu_hi + (size_t)t * 64 * DZ);
        const float4* srcl = (const float4*)(g_mu_lo + (size_t)t * 64 * DZ);
        #pragma unroll
        for (int i = 0; i < 2; i++) {
            const int fid = i * 256 + tid;            // 0..511
            const int n   = fid >> 3;                 // 0..63
            const int k4  = fid & 7;
            const uint32_t doff =
                (uint32_t)(n * DZ + ((k4 << 2) ^ ((n & 7) << 2))) * 4u;
            cp16(sh_base[buf] + doff, srch + fid);
            cp16(sl_base[buf] + doff, srcl + fid);
        }
        asm volatile("cp.async.commit_group;" ::: "memory");
    };

    float acc[4] = {0.f, 0.f, 0.f, 0.f};

    copy_chunk(0, 0);
    for (int t = 0; t < T; t++) {
        const int buf = t & 1;
        if (t + 1 < T) {
            copy_chunk(t + 1, buf ^ 1);
            asm volatile("cp.async.wait_group 1;" ::: "memory");
        } else {
            asm volatile("cp.async.wait_group 0;" ::: "memory");
        }
        __syncthreads();

        const float* __restrict__ bh = smh[buf];
        const float* __restrict__ bl = sml[buf];

        #pragma unroll
        for (int noff = 0; noff < 64; noff += 8) {
            const int nb   = noff + g;
            const int rowb = nb * DZ;

            // B fragments (XOR-swizzled, conflict-free)
            uint32_t Bh[4][2], Bl[4][2];
            #pragma unroll
            for (int j = 0; j < 4; j++) {
                const int idx0 = rowb + (((j << 3) | l4) ^ g4);
                Bh[j][0] = __float_as_uint(bh[idx0]);
                Bh[j][1] = __float_as_uint(bh[idx0 ^ 4]);
                Bl[j][0] = __float_as_uint(bl[idx0]);
                Bl[j][1] = __float_as_uint(bl[idx0 ^ 4]);
            }

            float c0[4] = {0.f, 0.f, 0.f, 0.f};
            float c1[4] = {0.f, 0.f, 0.f, 0.f};
            #pragma unroll
            for (int j = 0; j < 4; j++) {
                mma8(c0, ahi[0][j], Bh[j]);
                mma8(c1, ahi[1][j], Bh[j]);
            }
            #pragma unroll
            for (int j = 0; j < 4; j++) {
                mma8(c0, alo[0][j], Bh[j]);
                mma8(c1, alo[1][j], Bh[j]);
            }
            #pragma unroll
            for (int j = 0; j < 4; j++) {
                mma8(c0, ahi[0][j], Bl[j]);
                mma8(c1, ahi[1][j], Bl[j]);
            }

            // Underflow skip: if every logit in this 32x8 block is below the
            // fp32 floor after bias, the whole block contributes ~0.
            float mx = fmaxf(fmaxf(fmaxf(c0[0], c0[1]), fmaxf(c0[2], c0[3])),
                             fmaxf(fmaxf(c1[0], c1[1]), fmaxf(c1[2], c1[3])));
            if (__any_sync(0xFFFFFFFFu, mx > thr)) {
                acc[0] += ex2f(c0[0] + bias) + ex2f(c0[1] + bias);  // row g
                acc[1] += ex2f(c0[2] + bias) + ex2f(c0[3] + bias);  // row g+8
                acc[2] += ex2f(c1[0] + bias) + ex2f(c1[1] + bias);  // row g+16
                acc[3] += ex2f(c1[2] + bias) + ex2f(c1[3] + bias);  // row g+24
            }
        }
        __syncthreads();
    }

    // ---- quad reduce (mu cols), ln, then butterfly over the 8 g-groups ----
    #pragma unroll
    for (int q = 0; q < 4; q++) {
        acc[q] += __shfl_xor_sync(0xFFFFFFFFu, acc[q], 1);
        acc[q] += __shfl_xor_sync(0xFFFFFFFFu, acc[q], 2);
    }
    float lv = logf(fmaxf(acc[0], 1e-38f)) + logf(fmaxf(acc[1], 1e-38f))
             + logf(fmaxf(acc[2], 1e-38f)) + logf(fmaxf(acc[3], 1e-38f));
    #pragma unroll
    for (int o = 4; o < 32; o <<= 1)
        lv += __shfl_xor_sync(0xFFFFFFFFu, lv, o);
    // lv now = sum of ln(s) over this warp's 32 rows (each counted once)

    if (lane == 0) s_red[wid] = lv;
    __syncthreads();
    if (tid == 0) {
        float tot = 0.f;
        #pragma unroll
        for (int w = 0; w < 8; w++) tot += s_red[w];
        g_partials[blockIdx.x] = tot;
    }
}

// ---------------------------------------------------------------------------
// Final: okl = logC_kappa + kappa - ln(B) - logC_zero + mean_j ln(s_j)
// ---------------------------------------------------------------------------
__global__ void vmf_final(const float* __restrict__ kap_p,
                          const float* __restrict__ lck_p,
                          const float* __restrict__ lcz_p,
                          float* __restrict__ out,
                          int nblocks, int B, int NC)
{
    __shared__ float red[4];
    const int tid = threadIdx.x;
    float v = 0.f;
    for (int i = tid; i < nblocks; i += blockDim.x) v += g_partials[i];
    #pragma unroll
    for (int o = 16; o > 0; o >>= 1) v += __shfl_xor_sync(0xFFFFFFFFu, v, o);
    if ((tid & 31) == 0) red[tid >> 5] = v;
    __syncthreads();
    if (tid == 0) {
        float tot = red[0] + red[1] + red[2] + red[3];
        float okl = __ldg(lck_p) + __ldg(kap_p)
                  - logf((float)B) - __ldg(lcz_p)
                  + tot / (float)NC;
        out[0] = okl;
    }
}

// ---------------------------------------------------------------------------
extern "C" void kernel_launch(void* const* d_in, const int* in_sizes, int n_in,
                              void* d_out, int out_size)
{
    const float* mu  = (const float*)d_in[0];
    const float* z   = (const float*)d_in[1];
    const float* kap = (const float*)d_in[2];
    const float* lck = (const float*)d_in[3];
    const float* lcz = (const float*)d_in[4];

    const int B  = in_sizes[0] / DZ;    // 2048
    const int NC = in_sizes[1] / DZ;    // 65536 sample vectors

    vmf_prep_mu<<<(B + 7) / 8, 256>>>(mu, kap, B);

    const int grid = NC / 256;          // 256 z rows per block
    vmf_main<<<grid, 256>>>(z, kap, B, NC);

    vmf_final<<<1, 128>>>(kap, lck, lcz, (float*)d_out, grid, B, NC);
}

// round 5
// speedup vs baseline: 2.9697x; 1.6115x over previous
#include <cuda_runtime.h>
#include <cuda_fp16.h>
#include <cstdint>

#define DZ 32
#define L2E 1.4426950408889634f

// ---------------------------------------------------------------------------
// Static device scratch (no runtime allocation allowed)
// g_mu: per mu row n: 16 dwords; dword d = (c ^ key(n)) holds
//       (half2 hi[k=2c,2c+1], half2 lo[k=2c,2c+1]), w = mu_hat * kappa * log2e
// ---------------------------------------------------------------------------
__device__ uint2 g_mu[4096 * 16];
__device__ float g_partials[1024];

static __device__ __forceinline__ uint32_t s2u(const void* p) {
    uint32_t a;
    asm("{ .reg .u64 t; cvta.to.shared.u64 t, %1; cvt.u32.u64 %0, t; }" : "=r"(a) : "l"(p));
    return a;
}
static __device__ __forceinline__ void cp16(uint32_t saddr, const void* gaddr) {
    asm volatile("cp.async.cg.shared.global [%0], [%1], 16;"
                 :: "r"(saddr), "l"(__cvta_generic_to_global(gaddr)) : "memory");
}
static __device__ __forceinline__ float ex2f(float x) {
    float r; asm("ex2.approx.f32 %0, %1;" : "=f"(r) : "f"(x)); return r;
}
// m16n8k16 fp16 MMA, f32 accum
static __device__ __forceinline__ void mma16(float* d, const uint32_t* a,
                                             uint32_t b0, uint32_t b1) {
    asm volatile(
        "mma.sync.aligned.m16n8k16.row.col.f32.f16.f16.f32 "
        "{%0,%1,%2,%3},{%4,%5,%6,%7},{%8,%9},{%0,%1,%2,%3};"
        : "+f"(d[0]), "+f"(d[1]), "+f"(d[2]), "+f"(d[3])
        : "r"(a[0]), "r"(a[1]), "r"(a[2]), "r"(a[3]), "r"(b0), "r"(b1));
}
static __device__ __forceinline__ int keyfn(int n) {
    return ((n & 1) * 3) | (((n >> 1) & 3) << 2);
}

// ---------------------------------------------------------------------------
// Prep: normalize mu, scale by kappa*log2e, fp16 hi/lo split, pack + swizzle.
// One warp per row.
// ---------------------------------------------------------------------------
__global__ void vmf_prep_mu(const float* __restrict__ mu,
                            const float* __restrict__ kap_p, int B)
{
    const int n = (blockIdx.x * blockDim.x + threadIdx.x) >> 5;
    const int k = threadIdx.x & 31;
    if (n >= B) return;

    float v = __ldg(mu + (size_t)n * DZ + k);
    float ss = v * v;
    #pragma unroll
    for (int o = 16; o > 0; o >>= 1) ss += __shfl_xor_sync(0xFFFFFFFFu, ss, o);
    float r = rsqrtf(ss);
    r = r * fmaf(-0.5f * ss * r, r, 1.5f);           // Newton -> ~1e-7 rel
    float w = v * r * (__ldg(kap_p) * L2E);

    __half h = __float2half_rn(w);
    __half l = __float2half_rn(w - __half2float(h));
    uint32_t hs = (uint32_t)__half_as_ushort(h);
    uint32_t ls = (uint32_t)__half_as_ushort(l);

    // lanes 0..15: gather pair (2c, 2c+1), store swizzled dword
    uint32_t h0 = __shfl_sync(0xFFFFFFFFu, hs, (k * 2) & 31);
    uint32_t h1 = __shfl_sync(0xFFFFFFFFu, hs, (k * 2 + 1) & 31);
    uint32_t l0 = __shfl_sync(0xFFFFFFFFu, ls, (k * 2) & 31);
    uint32_t l1 = __shfl_sync(0xFFFFFFFFu, ls, (k * 2 + 1) & 31);
    if (k < 16) {
        uint2 dw = make_uint2(h0 | (h1 << 16), l0 | (l1 << 16));
        g_mu[n * 16 + (k ^ keyfn(n))] = dw;
    }
}

// ---------------------------------------------------------------------------
// Main: 256 z rows/CTA (8 warps x 32 rows as held fp16-split A fragments).
// mu streamed in 64-row chunks (8KB, packed/swizzled) via cp.async x2 buffers.
// 12 HMMA.16816 per 32x8 block; bias pre-loaded into C; ex2 + sum epilogue.
// ---------------------------------------------------------------------------
__global__ void __launch_bounds__(256, 2) vmf_main(
    const float* __restrict__ z, const float* __restrict__ kap_p,
    int B, int NC)
{
    __shared__ __align__(16) uint2 smu[2][64 * 16];   // 8KB per buffer
    __shared__ float s_red[8];

    const int tid  = threadIdx.x;
    const int wid  = tid >> 5;
    const int lane = tid & 31;
    const int g    = lane >> 2;        // fragment group row / mu row offset
    const int l4   = lane & 3;
    const int keyg = keyfn(g);         // noff is mult of 8 -> key(noff+g)=key(g)

    const float bias = -__ldg(kap_p) * L2E;

    // ---- A fragments: this warp's 32 z rows, fp16 hi/lo split, held ----
    // ahi[mt][kb][0..3]: m16n8k16 A regs for m-tile mt, K-step kb
    const int zr = blockIdx.x * 256 + wid * 32;
    uint32_t ahi[2][2][4], alo[2][2][4];
    #pragma unroll
    for (int mt = 0; mt < 2; mt++) {
        const int r0 = zr + mt * 16 + g;
        const int r1 = r0 + 8;
        #pragma unroll
        for (int e = 0; e < 4; e++) {               // float2 col idx = l4 + 4e
            const int c2 = l4 + 4 * e;
            float2 f0 = __ldg((const float2*)(z + (size_t)r0 * DZ) + c2);
            float2 f1 = __ldg((const float2*)(z + (size_t)r1 * DZ) + c2);
            __half2 h0 = __floats2half2_rn(f0.x, f0.y);
            __half2 h1 = __floats2half2_rn(f1.x, f1.y);
            __half2 e0 = __floats2half2_rn(f0.x - __half2float(__low2half(h0)),
                                           f0.y - __half2float(__high2half(h0)));
            __half2 e1 = __floats2half2_rn(f1.x - __half2float(__low2half(h1)),
                                           f1.y - __half2float(__high2half(h1)));
            const int kb = e >> 1, half = e & 1;    // a0/a1 (half=0) or a2/a3
            ahi[mt][kb][half * 2 + 0] = *(uint32_t*)&h0;
            ahi[mt][kb][half * 2 + 1] = *(uint32_t*)&h1;
            alo[mt][kb][half * 2 + 0] = *(uint32_t*)&e0;
            alo[mt][kb][half * 2 + 1] = *(uint32_t*)&e1;
        }
    }

    const uint32_t sbase[2] = { s2u(&smu[0][0]), s2u(&smu[1][0]) };
    const int T = B >> 6;                           // 64-row mu chunks

    auto copy_chunk = [&](int t, int buf) {
        const char* src = (const char*)(g_mu + (size_t)t * 1024);
        #pragma unroll
        for (int i = 0; i < 2; i++) {
            const int fid = i * 256 + tid;          // 0..511 x 16B = 8KB
            cp16(sbase[buf] + (uint32_t)fid * 16u, src + (size_t)fid * 16);
        }
        asm volatile("cp.async.commit_group;" ::: "memory");
    };

    float acc[4] = {0.f, 0.f, 0.f, 0.f};

    copy_chunk(0, 0);
    for (int t = 0; t < T; t++) {
        const int buf = t & 1;
        if (t + 1 < T) {
            copy_chunk(t + 1, buf ^ 1);
            asm volatile("cp.async.wait_group 1;" ::: "memory");
        } else {
            asm volatile("cp.async.wait_group 0;" ::: "memory");
        }
        __syncthreads();

        const uint32_t rowb = sbase[buf] + (uint32_t)g * 128u;

        #pragma unroll
        for (int noff = 0; noff < 64; noff += 8) {
            // B fragments: 4x LDS.64, swizzle-optimal
            uint32_t Bh[4], Bl[4];
            #pragma unroll
            for (int j = 0; j < 4; j++) {
                const uint32_t d = (uint32_t)((l4 + 4 * j) ^ keyg);
                uint2 u;
                asm volatile("ld.shared.v2.u32 {%0,%1}, [%2];"
                             : "=r"(u.x), "=r"(u.y)
                             : "r"(rowb + (uint32_t)noff * 128u + d * 8u));
                Bh[j] = u.x; Bl[j] = u.y;
            }

            #pragma unroll
            for (int mt = 0; mt < 2; mt++) {
                float c[4] = {bias, bias, bias, bias};
                mma16(c, ahi[mt][0], Bh[0], Bh[1]);
                mma16(c, ahi[mt][1], Bh[2], Bh[3]);
                mma16(c, alo[mt][0], Bh[0], Bh[1]);
                mma16(c, alo[mt][1], Bh[2], Bh[3]);
                mma16(c, ahi[mt][0], Bl[0], Bl[1]);
                mma16(c, ahi[mt][1], Bl[2], Bl[3]);
                acc[2 * mt + 0] += ex2f(c[0]) + ex2f(c[1]);   // row g (+16mt)
                acc[2 * mt + 1] += ex2f(c[2]) + ex2f(c[3]);   // row g+8 (+16mt)
            }
        }
        __syncthreads();
    }

    // ---- quad reduce (mu cols), ln, butterfly over the 8 g-groups ----
    #pragma unroll
    for (int q = 0; q < 4; q++) {
        acc[q] += __shfl_xor_sync(0xFFFFFFFFu, acc[q], 1);
        acc[q] += __shfl_xor_sync(0xFFFFFFFFu, acc[q], 2);
    }
    float lv = logf(fmaxf(acc[0], 1e-38f)) + logf(fmaxf(acc[1], 1e-38f))
             + logf(fmaxf(acc[2], 1e-38f)) + logf(fmaxf(acc[3], 1e-38f));
    #pragma unroll
    for (int o = 4; o < 32; o <<= 1)
        lv += __shfl_xor_sync(0xFFFFFFFFu, lv, o);

    if (lane == 0) s_red[wid] = lv;
    __syncthreads();
    if (tid == 0) {
        float tot = 0.f;
        #pragma unroll
        for (int w = 0; w < 8; w++) tot += s_red[w];
        g_partials[blockIdx.x] = tot;
    }
}

// ---------------------------------------------------------------------------
// Final: okl = logC_kappa + kappa - ln(B) - logC_zero + mean_j ln(s_j)
// ---------------------------------------------------------------------------
__global__ void vmf_final(const float* __restrict__ kap_p,
                          const float* __restrict__ lck_p,
                          const float* __restrict__ lcz_p,
                          float* __restrict__ out,
                          int nblocks, int B, int NC)
{
    __shared__ float red[4];
    const int tid = threadIdx.x;
    float v = 0.f;
    for (int i = tid; i < nblocks; i += blockDim.x) v += g_partials[i];
    #pragma unroll
    for (int o = 16; o > 0; o >>= 1) v += __shfl_xor_sync(0xFFFFFFFFu, v, o);
    if ((tid & 31) == 0) red[tid >> 5] = v;
    __syncthreads();
    if (tid == 0) {
        float tot = red[0] + red[1] + red[2] + red[3];
        float okl = __ldg(lck_p) + __ldg(kap_p)
                  - logf((float)B) - __ldg(lcz_p)
                  + tot / (float)NC;
        out[0] = okl;
    }
}

// ---------------------------------------------------------------------------
extern "C" void kernel_launch(void* const* d_in, const int* in_sizes, int n_in,
                              void* d_out, int out_size)
{
    const float* mu  = (const float*)d_in[0];
    const float* z   = (const float*)d_in[1];
    const float* kap = (const float*)d_in[2];
    const float* lck = (const float*)d_in[3];
    const float* lcz = (const float*)d_in[4];

    const int B  = in_sizes[0] / DZ;    // 2048
    const int NC = in_sizes[1] / DZ;    // 65536 sample vectors

    vmf_prep_mu<<<(B + 7) / 8, 256>>>(mu, kap, B);

    const int grid = NC / 256;          // 256 z rows per block
    vmf_main<<<grid, 256>>>(z, kap, B, NC);

    vmf_final<<<1, 128>>>(kap, lck, lcz, (float*)d_out, grid, B, NC);
}

// round 6
// speedup vs baseline: 4.3979x; 1.4809x over previous
#include <cuda_runtime.h>
#include <cuda_fp16.h>
#include <cstdint>

#define DZ 32
#define L2E 1.4426950408889634f

// ---------------------------------------------------------------------------
// Static device scratch (no runtime allocation allowed)
// g_mu: per mu row n: 16 dwords; dword d = (c ^ key(n)) holds
//       (half2 hi[k=2c,2c+1], half2 lo[k=2c,2c+1]), w = mu_hat * kappa * log2e
// g_thr: per z column j: biased-logit threshold (parent logit - 41), log2 dom.
// ---------------------------------------------------------------------------
__device__ uint2 g_mu[4096 * 16];
__device__ float g_thr[262144];
__device__ float g_partials[1024];

static __device__ __forceinline__ uint32_t s2u(const void* p) {
    uint32_t a;
    asm("{ .reg .u64 t; cvta.to.shared.u64 t, %1; cvt.u32.u64 %0, t; }" : "=r"(a) : "l"(p));
    return a;
}
static __device__ __forceinline__ void cp16(uint32_t saddr, const void* gaddr) {
    asm volatile("cp.async.cg.shared.global [%0], [%1], 16;"
                 :: "r"(saddr), "l"(__cvta_generic_to_global(gaddr)) : "memory");
}
static __device__ __forceinline__ float ex2f(float x) {
    float r; asm("ex2.approx.f32 %0, %1;" : "=f"(r) : "f"(x)); return r;
}
// m16n8k16 fp16 MMA, f32 accum
static __device__ __forceinline__ void mma16(float* d, const uint32_t* a,
                                             uint32_t b0, uint32_t b1) {
    asm volatile(
        "mma.sync.aligned.m16n8k16.row.col.f32.f16.f16.f32 "
        "{%0,%1,%2,%3},{%4,%5,%6,%7},{%8,%9},{%0,%1,%2,%3};"
        : "+f"(d[0]), "+f"(d[1]), "+f"(d[2]), "+f"(d[3])
        : "r"(a[0]), "r"(a[1]), "r"(a[2]), "r"(a[3]), "r"(b0), "r"(b1));
}
static __device__ __forceinline__ int keyfn(int n) {
    return ((n & 1) * 3) | (((n >> 1) & 3) << 2);
}

// ---------------------------------------------------------------------------
// Prep 1: normalize mu, scale by kappa*log2e, fp16 hi/lo split, pack+swizzle.
// One warp per row.
// ---------------------------------------------------------------------------
__global__ void vmf_prep_mu(const float* __restrict__ mu,
                            const float* __restrict__ kap_p, int B)
{
    const int n = (blockIdx.x * blockDim.x + threadIdx.x) >> 5;
    const int k = threadIdx.x & 31;
    if (n >= B) return;

    float v = __ldg(mu + (size_t)n * DZ + k);
    float ss = v * v;
    #pragma unroll
    for (int o = 16; o > 0; o >>= 1) ss += __shfl_xor_sync(0xFFFFFFFFu, ss, o);
    float r = rsqrtf(ss);
    r = r * fmaf(-0.5f * ss * r, r, 1.5f);           // Newton -> ~1e-7 rel
    float w = v * r * (__ldg(kap_p) * L2E);

    __half h = __float2half_rn(w);
    __half l = __float2half_rn(w - __half2float(h));
    uint32_t hs = (uint32_t)__half_as_ushort(h);
    uint32_t ls = (uint32_t)__half_as_ushort(l);

    uint32_t h0 = __shfl_sync(0xFFFFFFFFu, hs, (k * 2) & 31);
    uint32_t h1 = __shfl_sync(0xFFFFFFFFu, hs, (k * 2 + 1) & 31);
    uint32_t l0 = __shfl_sync(0xFFFFFFFFu, ls, (k * 2) & 31);
    uint32_t l1 = __shfl_sync(0xFFFFFFFFu, ls, (k * 2 + 1) & 31);
    if (k < 16) {
        uint2 dw = make_uint2(h0 | (h1 << 16), l0 | (l1 << 16));
        g_mu[n * 16 + (k ^ keyfn(n))] = dw;
    }
}

// ---------------------------------------------------------------------------
// Prep 2: per-column threshold from the KNOWN parent mu (j / n_samples):
// thr_j = kappa*log2e*(dot(mu_hat_parent, z_j) - 1) - 41.
// Parent logit is a lower bound on the column max; dropping terms below
// max-41 (log2) keeps relative error <= 2^-30. One warp per column.
// ---------------------------------------------------------------------------
__global__ void vmf_prep_thr(const float* __restrict__ mu,
                             const float* __restrict__ z,
                             const float* __restrict__ kap_p,
                             int NC, int ns)
{
    const int j = (blockIdx.x * blockDim.x + threadIdx.x) >> 5;
    const int k = threadIdx.x & 31;
    if (j >= NC) return;
    const int p = j / ns;

    float m = __ldg(mu + (size_t)p * DZ + k);
    float zz = __ldg(z + (size_t)j * DZ + k);
    float a = m * zz;
    float b = m * m;
    #pragma unroll
    for (int o = 16; o > 0; o >>= 1) {
        a += __shfl_xor_sync(0xFFFFFFFFu, a, o);
        b += __shfl_xor_sync(0xFFFFFFFFu, b, o);
    }
    if (k == 0)
        g_thr[j] = __ldg(kap_p) * L2E * (a * rsqrtf(b) - 1.0f) - 41.0f;
}

// ---------------------------------------------------------------------------
// Main: 256 z rows/CTA (8 warps x 32 rows held as fp16-split A fragments).
// mu streamed in 64-row chunks (8KB packed hi/lo) via cp.async x2 buffers.
// Per 16x8 block: 2 hi*hi MMAs -> warp vote vs per-column thresholds ->
// only ~12% of blocks get the 4 lo-correction MMAs + ex2 + accumulate.
// ---------------------------------------------------------------------------
__global__ void __launch_bounds__(256, 2) vmf_main(
    const float* __restrict__ z, const float* __restrict__ kap_p,
    int B, int NC)
{
    __shared__ __align__(16) uint2 smu[2][64 * 16];   // 8KB per buffer
    __shared__ float s_red[8];

    const int tid  = threadIdx.x;
    const int wid  = tid >> 5;
    const int lane = tid & 31;
    const int g    = lane >> 2;
    const int l4   = lane & 3;
    const int keyg = keyfn(g);

    const float bias = -__ldg(kap_p) * L2E;

    // ---- A fragments: this warp's 32 z rows, fp16 hi/lo split, held ----
    const int zr = blockIdx.x * 256 + wid * 32;
    uint32_t ahi[2][2][4], alo[2][2][4];
    float thr[2][2];
    #pragma unroll
    for (int mt = 0; mt < 2; mt++) {
        const int r0 = zr + mt * 16 + g;
        const int r1 = r0 + 8;
        thr[mt][0] = __ldg(g_thr + r0);
        thr[mt][1] = __ldg(g_thr + r1);
        #pragma unroll
        for (int e = 0; e < 4; e++) {
            const int c2 = l4 + 4 * e;
            float2 f0 = __ldg((const float2*)(z + (size_t)r0 * DZ) + c2);
            float2 f1 = __ldg((const float2*)(z + (size_t)r1 * DZ) + c2);
            __half2 h0 = __floats2half2_rn(f0.x, f0.y);
            __half2 h1 = __floats2half2_rn(f1.x, f1.y);
            __half2 e0 = __floats2half2_rn(f0.x - __half2float(__low2half(h0)),
                                           f0.y - __half2float(__high2half(h0)));
            __half2 e1 = __floats2half2_rn(f1.x - __half2float(__low2half(h1)),
                                           f1.y - __half2float(__high2half(h1)));
            const int kb = e >> 1, half = e & 1;
            ahi[mt][kb][half * 2 + 0] = *(uint32_t*)&h0;
            ahi[mt][kb][half * 2 + 1] = *(uint32_t*)&h1;
            alo[mt][kb][half * 2 + 0] = *(uint32_t*)&e0;
            alo[mt][kb][half * 2 + 1] = *(uint32_t*)&e1;
        }
    }

    const uint32_t sbase[2] = { s2u(&smu[0][0]), s2u(&smu[1][0]) };
    const int T = B >> 6;

    auto copy_chunk = [&](int t, int buf) {
        const char* src = (const char*)(g_mu + (size_t)t * 1024);
        #pragma unroll
        for (int i = 0; i < 2; i++) {
            const int fid = i * 256 + tid;
            cp16(sbase[buf] + (uint32_t)fid * 16u, src + (size_t)fid * 16);
        }
        asm volatile("cp.async.commit_group;" ::: "memory");
    };

    float acc[4] = {0.f, 0.f, 0.f, 0.f};

    copy_chunk(0, 0);
    for (int t = 0; t < T; t++) {
        const int buf = t & 1;
        if (t + 1 < T) {
            copy_chunk(t + 1, buf ^ 1);
            asm volatile("cp.async.wait_group 1;" ::: "memory");
        } else {
            asm volatile("cp.async.wait_group 0;" ::: "memory");
        }
        __syncthreads();

        const uint32_t rowb = sbase[buf] + (uint32_t)g * 128u;

        #pragma unroll
        for (int noff = 0; noff < 64; noff += 8) {
            // B fragments: 4x LDS.64 fetch hi AND lo together
            uint32_t Bh[4], Bl[4];
            #pragma unroll
            for (int j = 0; j < 4; j++) {
                const uint32_t d = (uint32_t)((l4 + 4 * j) ^ keyg);
                uint2 u;
                asm volatile("ld.shared.v2.u32 {%0,%1}, [%2];"
                             : "=r"(u.x), "=r"(u.y)
                             : "r"(rowb + (uint32_t)noff * 128u + d * 8u));
                Bh[j] = u.x; Bl[j] = u.y;
            }

            #pragma unroll
            for (int mt = 0; mt < 2; mt++) {
                float c[4] = {bias, bias, bias, bias};
                mma16(c, ahi[mt][0], Bh[0], Bh[1]);
                mma16(c, ahi[mt][1], Bh[2], Bh[3]);
                // hi*hi approximates the biased logit to +-0.1 (margin is in thr)
                bool p = (fmaxf(c[0], c[1]) > thr[mt][0]) |
                         (fmaxf(c[2], c[3]) > thr[mt][1]);
                if (__any_sync(0xFFFFFFFFu, p)) {
                    mma16(c, alo[mt][0], Bh[0], Bh[1]);
                    mma16(c, alo[mt][1], Bh[2], Bh[3]);
                    mma16(c, ahi[mt][0], Bl[0], Bl[1]);
                    mma16(c, ahi[mt][1], Bl[2], Bl[3]);
                    acc[2 * mt + 0] += ex2f(c[0]) + ex2f(c[1]);   // row g(+16mt)
                    acc[2 * mt + 1] += ex2f(c[2]) + ex2f(c[3]);   // row g+8
                }
            }
        }
        __syncthreads();
    }

    // ---- quad reduce (mu cols), ln, butterfly over the 8 g-groups ----
    #pragma unroll
    for (int q = 0; q < 4; q++) {
        acc[q] += __shfl_xor_sync(0xFFFFFFFFu, acc[q], 1);
        acc[q] += __shfl_xor_sync(0xFFFFFFFFu, acc[q], 2);
    }
    float lv = logf(fmaxf(acc[0], 1e-38f)) + logf(fmaxf(acc[1], 1e-38f))
             + logf(fmaxf(acc[2], 1e-38f)) + logf(fmaxf(acc[3], 1e-38f));
    #pragma unroll
    for (int o = 4; o < 32; o <<= 1)
        lv += __shfl_xor_sync(0xFFFFFFFFu, lv, o);

    if (lane == 0) s_red[wid] = lv;
    __syncthreads();
    if (tid == 0) {
        float tot = 0.f;
        #pragma unroll
        for (int w = 0; w < 8; w++) tot += s_red[w];
        g_partials[blockIdx.x] = tot;
    }
}

// ---------------------------------------------------------------------------
// Final: okl = logC_kappa + kappa - ln(B) - logC_zero + mean_j ln(s_j)
// ---------------------------------------------------------------------------
__global__ void vmf_final(const float* __restrict__ kap_p,
                          const float* __restrict__ lck_p,
                          const float* __restrict__ lcz_p,
                          float* __restrict__ out,
                          int nblocks, int B, int NC)
{
    __shared__ float red[4];
    const int tid = threadIdx.x;
    float v = 0.f;
    for (int i = tid; i < nblocks; i += blockDim.x) v += g_partials[i];
    #pragma unroll
    for (int o = 16; o > 0; o >>= 1) v += __shfl_xor_sync(0xFFFFFFFFu, v, o);
    if ((tid & 31) == 0) red[tid >> 5] = v;
    __syncthreads();
    if (tid == 0) {
        float tot = red[0] + red[1] + red[2] + red[3];
        float okl = __ldg(lck_p) + __ldg(kap_p)
                  - logf((float)B) - __ldg(lcz_p)
                  + tot / (float)NC;
        out[0] = okl;
    }
}

// ---------------------------------------------------------------------------
extern "C" void kernel_launch(void* const* d_in, const int* in_sizes, int n_in,
                              void* d_out, int out_size)
{
    const float* mu  = (const float*)d_in[0];
    const float* z   = (const float*)d_in[1];
    const float* kap = (const float*)d_in[2];
    const float* lck = (const float*)d_in[3];
    const float* lcz = (const float*)d_in[4];

    const int B  = in_sizes[0] / DZ;    // 2048
    const int NC = in_sizes[1] / DZ;    // 65536 sample vectors
    const int ns = NC / B;              // samples per mu (32)

    vmf_prep_mu<<<(B + 7) / 8, 256>>>(mu, kap, B);
    vmf_prep_thr<<<(NC + 7) / 8, 256>>>(mu, z, kap, NC, ns);

    const int grid = NC / 256;          // 256 z rows per block
    vmf_main<<<grid, 256>>>(z, kap, B, NC);

    vmf_final<<<1, 128>>>(kap, lck, lcz, (float*)d_out, grid, B, NC);
}

// round 8
// speedup vs baseline: 4.8905x; 1.1120x over previous
#include <cuda_runtime.h>
#include <cuda_fp16.h>
#include <cstdint>

#define DZ 32
#define L2E 1.4426950408889634f

// ---------------------------------------------------------------------------
// Static device scratch (no runtime allocation allowed)
// g_mu: per mu row n: 16 dwords; dword d = (c ^ key(n)) holds
//       (half2 hi[k=2c,2c+1], half2 lo[k=2c,2c+1]), w = mu_hat * kappa * log2e
// ---------------------------------------------------------------------------
__device__ uint2 g_mu[4096 * 16];
__device__ float g_partials[1024];
__device__ int   g_ticket;            // zero-init; reset by last block each run

static __device__ __forceinline__ uint32_t s2u(const void* p) {
    uint32_t a;
    asm("{ .reg .u64 t; cvta.to.shared.u64 t, %1; cvt.u32.u64 %0, t; }" : "=r"(a) : "l"(p));
    return a;
}
static __device__ __forceinline__ void cp16(uint32_t saddr, const void* gaddr) {
    asm volatile("cp.async.cg.shared.global [%0], [%1], 16;"
                 :: "r"(saddr), "l"(__cvta_generic_to_global(gaddr)) : "memory");
}
static __device__ __forceinline__ float ex2f(float x) {
    float r; asm("ex2.approx.f32 %0, %1;" : "=f"(r) : "f"(x)); return r;
}
// m16n8k16 fp16 MMA, f32 accumulate
static __device__ __forceinline__ void mma16(float* d, const uint32_t* a,
                                             uint32_t b0, uint32_t b1) {
    asm volatile(
        "mma.sync.aligned.m16n8k16.row.col.f32.f16.f16.f32 "
        "{%0,%1,%2,%3},{%4,%5,%6,%7},{%8,%9},{%0,%1,%2,%3};"
        : "+f"(d[0]), "+f"(d[1]), "+f"(d[2]), "+f"(d[3])
        : "r"(a[0]), "r"(a[1]), "r"(a[2]), "r"(a[3]), "r"(b0), "r"(b1));
}
// m16n8k16 fp16 MMA, fp16 accumulate (prefilter: 2x rate where supported)
static __device__ __forceinline__ void mma16h(uint32_t* d, const uint32_t* a,
                                              uint32_t b0, uint32_t b1) {
    asm volatile(
        "mma.sync.aligned.m16n8k16.row.col.f16.f16.f16.f16 "
        "{%0,%1},{%2,%3,%4,%5},{%6,%7},{%0,%1};"
        : "+r"(d[0]), "+r"(d[1])
        : "r"(a[0]), "r"(a[1]), "r"(a[2]), "r"(a[3]), "r"(b0), "r"(b1));
}
static __device__ __forceinline__ int keyfn(int n) {
    return ((n & 1) * 3) | (((n >> 1) & 3) << 2);
}

// ---------------------------------------------------------------------------
// Prep: normalize mu, scale by kappa*log2e, fp16 hi/lo split, pack+swizzle.
// One warp per row.
// ---------------------------------------------------------------------------
__global__ void vmf_prep_mu(const float* __restrict__ mu,
                            const float* __restrict__ kap_p, int B)
{
    const int n = (blockIdx.x * blockDim.x + threadIdx.x) >> 5;
    const int k = threadIdx.x & 31;
    if (n >= B) return;

    float v = __ldg(mu + (size_t)n * DZ + k);
    float ss = v * v;
    #pragma unroll
    for (int o = 16; o > 0; o >>= 1) ss += __shfl_xor_sync(0xFFFFFFFFu, ss, o);
    float r = rsqrtf(ss);
    r = r * fmaf(-0.5f * ss * r, r, 1.5f);           // Newton -> ~1e-7 rel
    float w = v * r * (__ldg(kap_p) * L2E);

    __half h = __float2half_rn(w);
    __half l = __float2half_rn(w - __half2float(h));
    uint32_t hs = (uint32_t)__half_as_ushort(h);
    uint32_t ls = (uint32_t)__half_as_ushort(l);

    uint32_t h0 = __shfl_sync(0xFFFFFFFFu, hs, (k * 2) & 31);
    uint32_t h1 = __shfl_sync(0xFFFFFFFFu, hs, (k * 2 + 1) & 31);
    uint32_t l0 = __shfl_sync(0xFFFFFFFFu, ls, (k * 2) & 31);
    uint32_t l1 = __shfl_sync(0xFFFFFFFFu, ls, (k * 2 + 1) & 31);
    if (k < 16) {
        uint2 dw = make_uint2(h0 | (h1 << 16), l0 | (l1 << 16));
        g_mu[n * 16 + (k ^ keyfn(n))] = dw;
    }
}

// ---------------------------------------------------------------------------
// Main: 256 z rows/CTA (8 warps x 32 rows held as fp16-split A fragments).
// Per-warp thresholds computed inline from the known parent mu (j / ns).
// mu streamed in 64-row chunks via cp.async x2. Per 16x8 block: 2 fp16-accum
// hi*hi MMAs -> vote vs thresholds -> ~6% of blocks recompute in f32 with
// lo corrections + ex2-accumulate. Last block reduces partials -> out.
// ---------------------------------------------------------------------------
__global__ void __launch_bounds__(256, 2) vmf_main(
    const float* __restrict__ mu, const float* __restrict__ z,
    const float* __restrict__ kap_p,
    const float* __restrict__ lck_p, const float* __restrict__ lcz_p,
    float* __restrict__ out, int B, int NC, int ns)
{
    __shared__ __align__(16) uint2 smu[2][64 * 16];   // 8KB per buffer
    __shared__ float s_red[8];
    __shared__ int   s_last;

    const int tid  = threadIdx.x;
    const int wid  = tid >> 5;
    const int lane = tid & 31;
    const int g    = lane >> 2;
    const int l4   = lane & 3;
    const int keyg = keyfn(g);

    if (tid == 0) s_last = 0;

    const float ke   = __ldg(kap_p) * L2E;
    const float bias = -ke;

    // ---- parent mu_hat for this warp's 32 z rows (all share one parent) ----
    const int zr = blockIdx.x * 256 + wid * 32;
    float mh = 0.f;
    const bool uniform_parent = (ns == 32);
    if (uniform_parent) {
        float m = __ldg(mu + (size_t)(zr >> 5) * DZ + lane);
        float ss = m * m;
        #pragma unroll
        for (int o = 16; o > 0; o >>= 1) ss += __shfl_xor_sync(0xFFFFFFFFu, ss, o);
        float r = rsqrtf(ss);
        r = r * fmaf(-0.5f * ss * r, r, 1.5f);
        mh = m * r;
    }

    // ---- A fragments (fp16 hi/lo split) + parent dots, fused ----
    uint32_t ahi[2][2][4], alo[2][2][4];
    float dq[2][2] = {{0.f, 0.f}, {0.f, 0.f}};
    #pragma unroll
    for (int mt = 0; mt < 2; mt++) {
        const int r0 = zr + mt * 16 + g;
        const int r1 = r0 + 8;
        #pragma unroll
        for (int e = 0; e < 4; e++) {
            const int c2 = l4 + 4 * e;
            float2 f0 = __ldg((const float2*)(z + (size_t)r0 * DZ) + c2);
            float2 f1 = __ldg((const float2*)(z + (size_t)r1 * DZ) + c2);
            float mv0 = __shfl_sync(0xFFFFFFFFu, mh, (2 * c2) & 31);
            float mv1 = __shfl_sync(0xFFFFFFFFu, mh, (2 * c2 + 1) & 31);
            dq[mt][0] += mv0 * f0.x + mv1 * f0.y;
            dq[mt][1] += mv0 * f1.x + mv1 * f1.y;
            __half2 h0 = __floats2half2_rn(f0.x, f0.y);
            __half2 h1 = __floats2half2_rn(f1.x, f1.y);
            __half2 e0 = __floats2half2_rn(f0.x - __half2float(__low2half(h0)),
                                           f0.y - __half2float(__high2half(h0)));
            __half2 e1 = __floats2half2_rn(f1.x - __half2float(__low2half(h1)),
                                           f1.y - __half2float(__high2half(h1)));
            const int kb = e >> 1, half = e & 1;
            ahi[mt][kb][half * 2 + 0] = *(uint32_t*)&h0;
            ahi[mt][kb][half * 2 + 1] = *(uint32_t*)&h1;
            alo[mt][kb][half * 2 + 0] = *(uint32_t*)&e0;
            alo[mt][kb][half * 2 + 1] = *(uint32_t*)&e1;
        }
    }
    // thresholds on the RAW (unbiased) logit scale: ke*dot_parent - 41
    float thr[2][2];
    #pragma unroll
    for (int mt = 0; mt < 2; mt++) {
        #pragma unroll
        for (int q = 0; q < 2; q++) {
            float d = dq[mt][q];
            d += __shfl_xor_sync(0xFFFFFFFFu, d, 1);
            d += __shfl_xor_sync(0xFFFFFFFFu, d, 2);
            thr[mt][q] = uniform_parent ? (ke * d - 41.0f) : -1e30f;
        }
    }

    const uint32_t sbase[2] = { s2u(&smu[0][0]), s2u(&smu[1][0]) };
    const int T = B >> 6;

    auto copy_chunk = [&](int t, int buf) {
        const char* src = (const char*)(g_mu + (size_t)t * 1024);
        #pragma unroll
        for (int i = 0; i < 2; i++) {
            const int fid = i * 256 + tid;
            cp16(sbase[buf] + (uint32_t)fid * 16u, src + (size_t)fid * 16);
        }
        asm volatile("cp.async.commit_group;" ::: "memory");
    };

    float acc[4] = {0.f, 0.f, 0.f, 0.f};

    copy_chunk(0, 0);
    for (int t = 0; t < T; t++) {
        const int buf = t & 1;
        if (t + 1 < T) {
            copy_chunk(t + 1, buf ^ 1);
            asm volatile("cp.async.wait_group 1;" ::: "memory");
        } else {
            asm volatile("cp.async.wait_group 0;" ::: "memory");
        }
        __syncthreads();

        const uint32_t rowb = sbase[buf] + (uint32_t)g * 128u;

        #pragma unroll
        for (int noff = 0; noff < 64; noff += 8) {
            // B fragments: 4x LDS.64 fetch hi AND lo together
            uint32_t Bh[4], Bl[4];
            #pragma unroll
            for (int j = 0; j < 4; j++) {
                const uint32_t d = (uint32_t)((l4 + 4 * j) ^ keyg);
                uint2 u;
                asm volatile("ld.shared.v2.u32 {%0,%1}, [%2];"
                             : "=r"(u.x), "=r"(u.y)
                             : "r"(rowb + (uint32_t)noff * 128u + d * 8u));
                Bh[j] = u.x; Bl[j] = u.y;
            }

            #pragma unroll
            for (int mt = 0; mt < 2; mt++) {
                // fp16-accum prefilter (raw logits, |err| ~0.03 << 41 margin)
                uint32_t D[2] = {0u, 0u};
                mma16h(D, ahi[mt][0], Bh[0], Bh[1]);
                mma16h(D, ahi[mt][1], Bh[2], Bh[3]);
                __half2 h0 = *(__half2*)&D[0];
                __half2 h1 = *(__half2*)&D[1];
                float m0 = __half2float(__hmax(__low2half(h0), __high2half(h0)));
                float m1 = __half2float(__hmax(__low2half(h1), __high2half(h1)));
                bool pr = (m0 > thr[mt][0]) | (m1 > thr[mt][1]);
                if (__any_sync(0xFFFFFFFFu, pr)) {
                    // full-precision recompute: hi*hi + lo*hi + hi*lo, f32 acc
                    float c[4] = {bias, bias, bias, bias};
                    mma16(c, ahi[mt][0], Bh[0], Bh[1]);
                    mma16(c, ahi[mt][1], Bh[2], Bh[3]);
                    mma16(c, alo[mt][0], Bh[0], Bh[1]);
                    mma16(c, alo[mt][1], Bh[2], Bh[3]);
                    mma16(c, ahi[mt][0], Bl[0], Bl[1]);
                    mma16(c, ahi[mt][1], Bl[2], Bl[3]);
                    acc[2 * mt + 0] += ex2f(c[0]) + ex2f(c[1]);   // row g(+16mt)
                    acc[2 * mt + 1] += ex2f(c[2]) + ex2f(c[3]);   // row g+8
                }
            }
        }
        __syncthreads();
    }

    // ---- quad reduce (mu cols), ln, butterfly over the 8 g-groups ----
    #pragma unroll
    for (int q = 0; q < 4; q++) {
        acc[q] += __shfl_xor_sync(0xFFFFFFFFu, acc[q], 1);
        acc[q] += __shfl_xor_sync(0xFFFFFFFFu, acc[q], 2);
    }
    float lv = logf(fmaxf(acc[0], 1e-38f)) + logf(fmaxf(acc[1], 1e-38f))
             + logf(fmaxf(acc[2], 1e-38f)) + logf(fmaxf(acc[3], 1e-38f));
    #pragma unroll
    for (int o = 4; o < 32; o <<= 1)
        lv += __shfl_xor_sync(0xFFFFFFFFu, lv, o);

    if (lane == 0) s_red[wid] = lv;
    __syncthreads();
    if (tid == 0) {
        float tot = 0.f;
        #pragma unroll
        for (int w = 0; w < 8; w++) tot += s_red[w];
        g_partials[blockIdx.x] = tot;
        __threadfence();
        int tk = atomicAdd(&g_ticket, 1);
        s_last = (tk == (int)gridDim.x - 1);
        if (s_last) g_ticket = 0;           // reset for next graph replay
    }
    __syncthreads();

    // ---- last block: deterministic fixed-order final reduction ----
    if (s_last) {
        volatile float* vp = g_partials;
        float v = 0.f;
        for (int i = tid; i < (int)gridDim.x; i += blockDim.x) v += vp[i];
        #pragma unroll
        for (int o = 16; o > 0; o >>= 1) v += __shfl_xor_sync(0xFFFFFFFFu, v, o);
        if (lane == 0) s_red[wid] = v;
        __syncthreads();
        if (tid == 0) {
            float tot = 0.f;
            #pragma unroll
            for (int w = 0; w < 8; w++) tot += s_red[w];
            float okl = __ldg(lck_p) + __ldg(kap_p)
                      - logf((float)B) - __ldg(lcz_p)
                      + tot / (float)NC;
            out[0] = okl;
        }
    }
}

// ---------------------------------------------------------------------------
extern "C" void kernel_launch(void* const* d_in, const int* in_sizes, int n_in,
                              void* d_out, int out_size)
{
    const float* mu  = (const float*)d_in[0];
    const float* z   = (const float*)d_in[1];
    const float* kap = (const float*)d_in[2];
    const float* lck = (const float*)d_in[3];
    const float* lcz = (const float*)d_in[4];

    const int B  = in_sizes[0] / DZ;    // 2048
    const int NC = in_sizes[1] / DZ;    // 65536 sample vectors
    const int ns = NC / B;              // samples per mu (32)

    vmf_prep_mu<<<(B + 7) / 8, 256>>>(mu, kap, B);

    const int grid = NC / 256;          // 256 z rows per block
    vmf_main<<<grid, 256>>>(mu, z, kap, lck, lcz, (float*)d_out, B, NC, ns);
}

// round 10
// speedup vs baseline: 6.0581x; 1.2388x over previous
#include <cuda_runtime.h>
#include <cuda_fp16.h>
#include <cstdint>

#define DZ 32
#define L2E 1.4426950408889634f

// ---------------------------------------------------------------------------
// Static device scratch (no runtime allocation allowed)
// g_mu_hi/lo: per mu row n: 16 dwords (half2 k-pairs), reordered so that
// position 4*(p&3)+(p>>2) holds k-pair p  ->  thread l4 reads k-pairs
// {l4, l4+4, l4+8, l4+12} as ONE contiguous 16-byte LDS.128.
// Values: w = mu_hat * kappa * log2e, fp16 hi + fp16 residual lo.
// ---------------------------------------------------------------------------
__device__ uint32_t g_mu_hi[4096 * 16];
__device__ uint32_t g_mu_lo[4096 * 16];
__device__ float g_partials[1024];
__device__ int   g_ticket;            // zero-init; reset by last block each run

static __device__ __forceinline__ uint32_t s2u(const void* p) {
    uint32_t a;
    asm("{ .reg .u64 t; cvta.to.shared.u64 t, %1; cvt.u32.u64 %0, t; }" : "=r"(a) : "l"(p));
    return a;
}
static __device__ __forceinline__ void cp16(uint32_t saddr, const void* gaddr) {
    asm volatile("cp.async.cg.shared.global [%0], [%1], 16;"
                 :: "r"(saddr), "l"(__cvta_generic_to_global(gaddr)) : "memory");
}
static __device__ __forceinline__ float ex2f(float x) {
    float r; asm("ex2.approx.f32 %0, %1;" : "=f"(r) : "f"(x)); return r;
}
// m16n8k16 fp16 MMA, f32 accumulate
static __device__ __forceinline__ void mma16(float* d, const uint32_t* a,
                                             uint32_t b0, uint32_t b1) {
    asm volatile(
        "mma.sync.aligned.m16n8k16.row.col.f32.f16.f16.f32 "
        "{%0,%1,%2,%3},{%4,%5,%6,%7},{%8,%9},{%0,%1,%2,%3};"
        : "+f"(d[0]), "+f"(d[1]), "+f"(d[2]), "+f"(d[3])
        : "r"(a[0]), "r"(a[1]), "r"(a[2]), "r"(a[3]), "r"(b0), "r"(b1));
}
// m16n8k16 fp16 MMA, fp16 accumulate (prefilter)
static __device__ __forceinline__ void mma16h(uint32_t* d, const uint32_t* a,
                                              uint32_t b0, uint32_t b1) {
    asm volatile(
        "mma.sync.aligned.m16n8k16.row.col.f16.f16.f16.f16 "
        "{%0,%1},{%2,%3,%4,%5},{%6,%7},{%0,%1};"
        : "+r"(d[0]), "+r"(d[1])
        : "r"(a[0]), "r"(a[1]), "r"(a[2]), "r"(a[3]), "r"(b0), "r"(b1));
}

// ---------------------------------------------------------------------------
// Prep: normalize mu, scale by kappa*log2e, fp16 hi/lo split, store planes
// with the k-pair interleave. One warp per row.
// ---------------------------------------------------------------------------
__global__ void vmf_prep_mu(const float* __restrict__ mu,
                            const float* __restrict__ kap_p, int B)
{
    const int n = (blockIdx.x * blockDim.x + threadIdx.x) >> 5;
    const int k = threadIdx.x & 31;
    if (n >= B) return;

    float v = __ldg(mu + (size_t)n * DZ + k);
    float ss = v * v;
    #pragma unroll
    for (int o = 16; o > 0; o >>= 1) ss += __shfl_xor_sync(0xFFFFFFFFu, ss, o);
    float r = rsqrtf(ss);
    r = r * fmaf(-0.5f * ss * r, r, 1.5f);           // Newton -> ~1e-7 rel
    float w = v * r * (__ldg(kap_p) * L2E);

    __half h = __float2half_rn(w);
    __half l = __float2half_rn(w - __half2float(h));
    uint32_t hs = (uint32_t)__half_as_ushort(h);
    uint32_t ls = (uint32_t)__half_as_ushort(l);

    uint32_t h0 = __shfl_sync(0xFFFFFFFFu, hs, (k * 2) & 31);
    uint32_t h1 = __shfl_sync(0xFFFFFFFFu, hs, (k * 2 + 1) & 31);
    uint32_t l0 = __shfl_sync(0xFFFFFFFFu, ls, (k * 2) & 31);
    uint32_t l1 = __shfl_sync(0xFFFFFFFFu, ls, (k * 2 + 1) & 31);
    if (k < 16) {
        const int pos = 4 * (k & 3) + (k >> 2);      // k-pair interleave
        g_mu_hi[n * 16 + pos] = h0 | (h1 << 16);
        g_mu_lo[n * 16 + pos] = l0 | (l1 << 16);
    }
}

// ---------------------------------------------------------------------------
// Main: 256 z rows/CTA (8 warps x 32 rows held as fp16-split A fragments).
// mu streamed in 64-row chunks via cp.async x2 (hi plane 4KB + lo plane 4KB).
// Hot path per 32x8 block: ONE LDS.128 (hi) + 4 fp16-accum MMAs + vote.
// Accepted (~6%): one LDS.128 (lo) + 6 f32-accum MMAs + ex2-accumulate.
// Last block reduces partials -> out.
// ---------------------------------------------------------------------------
__global__ void __launch_bounds__(256, 2) vmf_main(
    const float* __restrict__ mu, const float* __restrict__ z,
    const float* __restrict__ kap_p,
    const float* __restrict__ lck_p, const float* __restrict__ lcz_p,
    float* __restrict__ out, int B, int NC, int ns)
{
    // [buf][plane hi=0,lo=1][64 rows * 16 dwords]
    __shared__ __align__(16) uint32_t smu[2 * 2 * 1024];
    __shared__ float s_red[8];
    __shared__ int   s_last;

    const int tid  = threadIdx.x;
    const int wid  = tid >> 5;
    const int lane = tid & 31;
    const int g    = lane >> 2;
    const int l4   = lane & 3;

    if (tid == 0) s_last = 0;

    const float ke   = __ldg(kap_p) * L2E;
    const float bias = -ke;

    // ---- parent mu_hat for this warp's 32 z rows (all share one parent) ----
    const int zr = blockIdx.x * 256 + wid * 32;
    float mh = 0.f;
    const bool uniform_parent = (ns == 32);
    if (uniform_parent) {
        float m = __ldg(mu + (size_t)(zr >> 5) * DZ + lane);
        float ss = m * m;
        #pragma unroll
        for (int o = 16; o > 0; o >>= 1) ss += __shfl_xor_sync(0xFFFFFFFFu, ss, o);
        float r = rsqrtf(ss);
        r = r * fmaf(-0.5f * ss * r, r, 1.5f);
        mh = m * r;
    }

    // ---- A fragments (fp16 hi/lo split) + parent dots, fused ----
    uint32_t ahi[2][2][4], alo[2][2][4];
    float dq[2][2] = {{0.f, 0.f}, {0.f, 0.f}};
    #pragma unroll
    for (int mt = 0; mt < 2; mt++) {
        const int r0 = zr + mt * 16 + g;
        const int r1 = r0 + 8;
        #pragma unroll
        for (int e = 0; e < 4; e++) {
            const int c2 = l4 + 4 * e;
            float2 f0 = __ldg((const float2*)(z + (size_t)r0 * DZ) + c2);
            float2 f1 = __ldg((const float2*)(z + (size_t)r1 * DZ) + c2);
            float mv0 = __shfl_sync(0xFFFFFFFFu, mh, (2 * c2) & 31);
            float mv1 = __shfl_sync(0xFFFFFFFFu, mh, (2 * c2 + 1) & 31);
            dq[mt][0] += mv0 * f0.x + mv1 * f0.y;
            dq[mt][1] += mv0 * f1.x + mv1 * f1.y;
            __half2 h0 = __floats2half2_rn(f0.x, f0.y);
            __half2 h1 = __floats2half2_rn(f1.x, f1.y);
            __half2 e0 = __floats2half2_rn(f0.x - __half2float(__low2half(h0)),
                                           f0.y - __half2float(__high2half(h0)));
            __half2 e1 = __floats2half2_rn(f1.x - __half2float(__low2half(h1)),
                                           f1.y - __half2float(__high2half(h1)));
            const int kb = e >> 1, half = e & 1;
            ahi[mt][kb][half * 2 + 0] = *(uint32_t*)&h0;
            ahi[mt][kb][half * 2 + 1] = *(uint32_t*)&h1;
            alo[mt][kb][half * 2 + 0] = *(uint32_t*)&e0;
            alo[mt][kb][half * 2 + 1] = *(uint32_t*)&e1;
        }
    }
    // thresholds (raw logit scale: ke*dot_parent - 41), pre-converted to half
    __half thrh[2][2];
    #pragma unroll
    for (int mt = 0; mt < 2; mt++) {
        #pragma unroll
        for (int q = 0; q < 2; q++) {
            float d = dq[mt][q];
            d += __shfl_xor_sync(0xFFFFFFFFu, d, 1);
            d += __shfl_xor_sync(0xFFFFFFFFu, d, 2);
            thrh[mt][q] = __float2half(uniform_parent ? (ke * d - 41.0f)
                                                      : -1e30f);  // -> -inf
        }
    }

    const uint32_t sbase = s2u(smu);
    const uint32_t warp_off = (uint32_t)(g * 64 + l4 * 16);
    const int T = B >> 6;

    auto copy_chunk = [&](int t, int buf) {
        const uint32_t dst = sbase + (uint32_t)buf * 8192u;
        cp16(dst + (uint32_t)tid * 16u,        g_mu_hi + (size_t)t * 1024 + tid * 4);
        cp16(dst + 4096u + (uint32_t)tid * 16u, g_mu_lo + (size_t)t * 1024 + tid * 4);
        asm volatile("cp.async.commit_group;" ::: "memory");
    };

    float acc[4] = {0.f, 0.f, 0.f, 0.f};

    copy_chunk(0, 0);
    for (int t = 0; t < T; t++) {
        const int buf = t & 1;
        if (t + 1 < T) {
            copy_chunk(t + 1, buf ^ 1);
            asm volatile("cp.async.wait_group 1;" ::: "memory");
        } else {
            asm volatile("cp.async.wait_group 0;" ::: "memory");
        }
        __syncthreads();

        const uint32_t hib = sbase + (uint32_t)buf * 8192u + warp_off;

        #pragma unroll
        for (int noff = 0; noff < 64; noff += 8) {
            // ONE LDS.128: full hi B-fragment (k-pairs l4, l4+4, l4+8, l4+12)
            uint32_t Bh[4];
            asm volatile("ld.shared.v4.u32 {%0,%1,%2,%3}, [%4];"
                         : "=r"(Bh[0]), "=r"(Bh[1]), "=r"(Bh[2]), "=r"(Bh[3])
                         : "r"(hib + (uint32_t)noff * 64u));

            // fp16-accum prefilter for both m-tiles (raw logits)
            uint32_t D0[2] = {0u, 0u}, D1[2] = {0u, 0u};
            mma16h(D0, ahi[0][0], Bh[0], Bh[1]);
            mma16h(D0, ahi[0][1], Bh[2], Bh[3]);
            mma16h(D1, ahi[1][0], Bh[0], Bh[1]);
            mma16h(D1, ahi[1][1], Bh[2], Bh[3]);

            __half2 a0 = *(__half2*)&D0[0], b0 = *(__half2*)&D0[1];
            __half2 a1 = *(__half2*)&D1[0], b1 = *(__half2*)&D1[1];
            bool p0 = __hgt(__hmax(__low2half(a0), __high2half(a0)), thrh[0][0]) |
                      __hgt(__hmax(__low2half(b0), __high2half(b0)), thrh[0][1]);
            bool p1 = __hgt(__hmax(__low2half(a1), __high2half(a1)), thrh[1][0]) |
                      __hgt(__hmax(__low2half(b1), __high2half(b1)), thrh[1][1]);
            unsigned v0 = __any_sync(0xFFFFFFFFu, p0);
            unsigned v1 = __any_sync(0xFFFFFFFFu, p1);

            if (v0 | v1) {
                uint32_t Bl[4];
                asm volatile("ld.shared.v4.u32 {%0,%1,%2,%3}, [%4];"
                             : "=r"(Bl[0]), "=r"(Bl[1]), "=r"(Bl[2]), "=r"(Bl[3])
                             : "r"(hib + 4096u + (uint32_t)noff * 64u));
                if (v0) {
                    float c[4] = {bias, bias, bias, bias};
                    mma16(c, ahi[0][0], Bh[0], Bh[1]);
                    mma16(c, ahi[0][1], Bh[2], Bh[3]);
                    mma16(c, alo[0][0], Bh[0], Bh[1]);
                    mma16(c, alo[0][1], Bh[2], Bh[3]);
                    mma16(c, ahi[0][0], Bl[0], Bl[1]);
                    mma16(c, ahi[0][1], Bl[2], Bl[3]);
                    acc[0] += ex2f(c[0]) + ex2f(c[1]);
                    acc[1] += ex2f(c[2]) + ex2f(c[3]);
                }
                if (v1) {
                    float c[4] = {bias, bias, bias, bias};
                    mma16(c, ahi[1][0], Bh[0], Bh[1]);
                    mma16(c, ahi[1][1], Bh[2], Bh[3]);
                    mma16(c, alo[1][0], Bh[0], Bh[1]);
                    mma16(c, alo[1][1], Bh[2], Bh[3]);
                    mma16(c, ahi[1][0], Bl[0], Bl[1]);
                    mma16(c, ahi[1][1], Bl[2], Bl[3]);
                    acc[2] += ex2f(c[0]) + ex2f(c[1]);
                    acc[3] += ex2f(c[2]) + ex2f(c[3]);
                }
            }
        }
        __syncthreads();
    }

    // ---- quad reduce (mu cols), ln, butterfly over the 8 g-groups ----
    #pragma unroll
    for (int q = 0; q < 4; q++) {
        acc[q] += __shfl_xor_sync(0xFFFFFFFFu, acc[q], 1);
        acc[q] += __shfl_xor_sync(0xFFFFFFFFu, acc[q], 2);
    }
    float lv = logf(fmaxf(acc[0], 1e-38f)) + logf(fmaxf(acc[1], 1e-38f))
             + logf(fmaxf(acc[2], 1e-38f)) + logf(fmaxf(acc[3], 1e-38f));
    #pragma unroll
    for (int o = 4; o < 32; o <<= 1)
        lv += __shfl_xor_sync(0xFFFFFFFFu, lv, o);

    if (lane == 0) s_red[wid] = lv;
    __syncthreads();
    if (tid == 0) {
        float tot = 0.f;
        #pragma unroll
        for (int w = 0; w < 8; w++) tot += s_red[w];
        g_partials[blockIdx.x] = tot;
        __threadfence();
        int tk = atomicAdd(&g_ticket, 1);
        s_last = (tk == (int)gridDim.x - 1);
        if (s_last) g_ticket = 0;           // reset for next graph replay
    }
    __syncthreads();

    // ---- last block: deterministic fixed-order final reduction ----
    if (s_last) {
        volatile float* vp = g_partials;
        float v = 0.f;
        for (int i = tid; i < (int)gridDim.x; i += blockDim.x) v += vp[i];
        #pragma unroll
        for (int o = 16; o > 0; o >>= 1) v += __shfl_xor_sync(0xFFFFFFFFu, v, o);
        if (lane == 0) s_red[wid] = v;
        __syncthreads();
        if (tid == 0) {
            float tot = 0.f;
            #pragma unroll
            for (int w = 0; w < 8; w++) tot += s_red[w];
            float okl = __ldg(lck_p) + __ldg(kap_p)
                      - logf((float)B) - __ldg(lcz_p)
                      + tot / (float)NC;
            out[0] = okl;
        }
    }
}

// ---------------------------------------------------------------------------
extern "C" void kernel_launch(void* const* d_in, const int* in_sizes, int n_in,
                              void* d_out, int out_size)
{
    const float* mu  = (const float*)d_in[0];
    const float* z   = (const float*)d_in[1];
    const float* kap = (const float*)d_in[2];
    const float* lck = (const float*)d_in[3];
    const float* lcz = (const float*)d_in[4];

    const int B  = in_sizes[0] / DZ;    // 2048
    const int NC = in_sizes[1] / DZ;    // 65536 sample vectors
    const int ns = NC / B;              // samples per mu (32)

    vmf_prep_mu<<<(B + 7) / 8, 256>>>(mu, kap, B);

    const int grid = NC / 256;          // 256 z rows per block
    vmf_main<<<grid, 256>>>(mu, z, kap, lck, lcz, (float*)d_out, B, NC, ns);
}